// round 5
// baseline (speedup 1.0000x reference)
#include <cuda_runtime.h>
#include <cstdint>

#define HW      409600      // 640*640
#define NVEC    (HW/4)      // 102400
#define NCH     12
#define NB      8
#define NCLS    2
#define NINST   16          // NCLS * NB
#define NMAPS   6
#define EPSF    1e-4f
#define LAMBDAF 0.7f
#define NBINS   65536       // 16-bit radix digit

// ---------------- scratch (static device globals; no allocation) ------------
__device__ unsigned int g_keys[(size_t)NINST * HW];     // ~26 MB
__device__ unsigned int g_hist16[NINST][NBINS];         // 4 MB
__device__ unsigned int g_pos[NINST];
__device__ unsigned int g_negtot[NINST];
__device__ unsigned int g_prefix[NINST];
__device__ unsigned int g_k[NINST];
__device__ float        g_thr[NINST];
__device__ int          g_fallback[NINST];
__device__ float        g_sums[NINST][18];  // [0..2] text a,b,c ; [3+3c..] kernel c

// ---------------- helpers ---------------------------------------------------
__device__ __forceinline__ unsigned int order_key(float x) {
    unsigned int u = __float_as_uint(x);
    u = (u & 0x80000000u) ? ~u : (u | 0x80000000u);
    if (u == 0u) u = 1u;   // reserve 0 as "positive pixel" sentinel
    return u;
}
__device__ __forceinline__ float key_to_float(unsigned int k) {
    unsigned int bits = (k & 0x80000000u) ? (k ^ 0x80000000u) : ~k;
    return __uint_as_float(bits);
}
__device__ __forceinline__ float sigmoidf_fast(float x) {
    return 1.0f / (1.0f + __expf(-x));
}

// ---------------- kernels ---------------------------------------------------
// Zero the 4MB histogram (1024 blocks x 256 threads x uint4) + small state.
__global__ void zero_kernel() {
    uint4* h4 = (uint4*)&g_hist16[0][0];
    size_t i = (size_t)blockIdx.x * blockDim.x + threadIdx.x;
    uint4 z; z.x = z.y = z.z = z.w = 0u;
    h4[i] = z;
    if (blockIdx.x == 0 && threadIdx.x < NINST) {
        int inst = threadIdx.x;
        g_pos[inst] = 0u; g_negtot[inst] = 0u;
        g_prefix[inst] = 0u; g_k[inst] = 0u; g_fallback[inst] = 0;
#pragma unroll
        for (int j = 0; j < 18; j++) g_sums[inst][j] = 0.0f;
    }
}

// Pass 0: stream ALL 13 channels once. Builds keys + top-16-bit histogram +
// pos/neg counts, AND computes the 15 kernel-dice sums (threshold-independent).
__global__ void __launch_bounds__(256) pass0_kernel(
        const float* __restrict__ outputs,
        const float* __restrict__ labels,
        const float* __restrict__ tmask) {
    const int inst = blockIdx.y;
    const int cls  = inst >> 3, b = inst & 7;
    const int ctxt = cls * NMAPS + (NMAPS - 1);
    const float4* __restrict__ s4   = (const float4*)(outputs + ((size_t)b * NCH + ctxt) * HW);
    const float4* __restrict__ g4   = (const float4*)(labels  + ((size_t)b * NCH + ctxt) * HW);
    const float4* __restrict__ m4   = (const float4*)(tmask   + (size_t)b * HW);
    const float4* __restrict__ ker4 = (const float4*)(outputs + ((size_t)b * NCH + cls * NMAPS) * HW);
    const float4* __restrict__ gk4  = (const float4*)(labels  + ((size_t)b * NCH + cls * NMAPS) * HW);
    uint4* __restrict__ keys4 = (uint4*)(g_keys + (size_t)inst * HW);
    unsigned int* __restrict__ hist = g_hist16[inst];

    __shared__ unsigned int spos, sneg;
    __shared__ float ssum[15];
    if (threadIdx.x == 0) { spos = 0u; sneg = 0u; }
    if (threadIdx.x < 15) ssum[threadIdx.x] = 0.0f;
    __syncthreads();

    float acc[15];
#pragma unroll
    for (int j = 0; j < 15; j++) acc[j] = 0.0f;
    unsigned int lpos = 0, lneg = 0;

    for (int v = blockIdx.x * blockDim.x + threadIdx.x; v < NVEC;
         v += gridDim.x * blockDim.x) {
        float4 sv4 = s4[v];
        float4 gv4 = g4[v];
        float4 mv4 = m4[v];
        float4 kv4[NMAPS - 1], gkv4[NMAPS - 1];
#pragma unroll
        for (int c = 0; c < NMAPS - 1; c++) {
            kv4[c]  = ker4[(size_t)c * NVEC + v];
            gkv4[c] = gk4 [(size_t)c * NVEC + v];
        }

        uint4 kout; kout.x = kout.y = kout.z = kout.w = 0u;
        const float* sv = &sv4.x; const float* gv = &gv4.x; const float* mv = &mv4.x;
        unsigned int* kp = &kout.x;
#pragma unroll
        for (int j = 0; j < 4; j++) {
            float s = sv[j], g = gv[j], m = mv[j];
            if (g <= 0.5f) {
                unsigned int key = order_key(s);
                kp[j] = key;
                atomicAdd(&hist[key >> 16], 1u);
                lneg++;
            } else if (m > 0.5f) {
                lpos++;
            }
            // kernel-dice (threshold-independent): sel_k = sigmoid(s)>0.5 & m>0.5
            float selk = ((s > 0.0f) && (m > 0.5f)) ? 1.0f : 0.0f;
#pragma unroll
            for (int c = 0; c < NMAPS - 1; c++) {
                float kv  = (&kv4[c].x)[j];
                float gkv = (&gkv4[c].x)[j];
                float sk  = sigmoidf_fast(kv);
                float p2 = sk * selk, t2 = gkv * selk;
                acc[c * 3 + 0] += p2 * t2;
                acc[c * 3 + 1] += p2 * p2;
                acc[c * 3 + 2] += t2 * t2;
            }
        }
        keys4[v] = kout;
    }

    const int lane = threadIdx.x & 31;
#pragma unroll
    for (int j = 0; j < 15; j++) {
        float vv = acc[j];
#pragma unroll
        for (int off = 16; off > 0; off >>= 1)
            vv += __shfl_down_sync(0xFFFFFFFFu, vv, off);
        if (lane == 0) atomicAdd(&ssum[j], vv);
    }
    atomicAdd(&spos, lpos);
    atomicAdd(&sneg, lneg);
    __syncthreads();
    if (threadIdx.x < 15)
        atomicAdd(&g_sums[inst][3 + threadIdx.x], ssum[threadIdx.x]);
    if (threadIdx.x == 0) {
        if (spos) atomicAdd(&g_pos[inst], spos);
        if (sneg) atomicAdd(&g_negtot[inst], sneg);
    }
}

// Select the digit from the 64K-bin histogram (descending order-statistic).
// passB==0: selects top-16 digit, zeroes the histogram for reuse.
// passB==1: selects low-16 digit, writes final threshold.
__global__ void select16_kernel(int passB) {
    const int inst = blockIdx.x;
    const int t = threadIdx.x;              // 256 threads
    unsigned int* __restrict__ hist = g_hist16[inst];

    __shared__ unsigned int chunk_sum[256];
    __shared__ unsigned int sh[256];
    __shared__ int s_chunk;
    __shared__ unsigned int s_k;

    if (t == 0) {
        unsigned int k;
        if (!passB) {
            unsigned int pos = g_pos[inst], negt = g_negtot[inst];
            unsigned long long nn = (unsigned long long)pos * 3ull;
            unsigned int neg_num = (unsigned int)(nn < (unsigned long long)negt
                                                      ? nn : (unsigned long long)negt);
            int fb = (pos == 0u) || (neg_num == 0u);
            g_fallback[inst] = fb;
            k = fb ? 1u : neg_num;
        } else {
            k = g_k[inst];
        }
        s_k = k;
    }
    __syncthreads();

    // per-thread chunk sum via uint4 (thread t owns bins [t*256, t*256+256))
    const int base = t << 8;
    const uint4* h4 = (const uint4*)&hist[base];
    unsigned int sum = 0;
#pragma unroll 8
    for (int i = 0; i < 64; i++) {
        uint4 q = h4[i];
        sum += q.x + q.y + q.z + q.w;
    }
    chunk_sum[t] = sum;
    __syncthreads();

    if (t == 0) {
        unsigned int k = s_k, cum = 0;
        int c = 255;
        for (; c > 0; --c) {
            if (cum + chunk_sum[c] >= k) break;
            cum += chunk_sum[c];
        }
        s_chunk = c; s_k = k - cum;
    }
    __syncthreads();

    const int c = s_chunk;
    sh[t] = hist[(c << 8) + t];
    __syncthreads();

    if (t == 0) {
        unsigned int k = s_k, cum = 0;
        int bin = 255;
        for (; bin > 0; --bin) {
            if (cum + sh[bin] >= k) break;
            cum += sh[bin];
        }
        unsigned int digit = (unsigned int)((c << 8) | bin);
        if (!passB) {
            g_prefix[inst] = digit << 16;
            g_k[inst] = k - cum;
        } else {
            g_thr[inst] = key_to_float(g_prefix[inst] | digit);
        }
    }

    if (!passB) {   // zero histogram for the refinement pass
        __syncthreads();
        uint4* hw4 = (uint4*)&hist[base];
        uint4 z; z.x = z.y = z.z = z.w = 0u;
#pragma unroll 8
        for (int i = 0; i < 64; i++) hw4[i] = z;
    }
}

// Refinement: histogram low 16 bits of keys matching the top-16 prefix.
__global__ void histB_kernel() {
    const int inst = blockIdx.y;
    const uint4* __restrict__ keys4 = (const uint4*)(g_keys + (size_t)inst * HW);
    const unsigned int pfx = g_prefix[inst] >> 16;
    unsigned int* __restrict__ hist = g_hist16[inst];

    for (int v = blockIdx.x * blockDim.x + threadIdx.x; v < NVEC;
         v += gridDim.x * blockDim.x) {
        uint4 k = keys4[v];
        const unsigned int* kp = &k.x;
#pragma unroll
        for (int j = 0; j < 4; j++) {
            unsigned int key = kp[j];
            if (key != 0u && (key >> 16) == pfx)
                atomicAdd(&hist[key & 0xFFFFu], 1u);
        }
    }
}

// Text dice only (needs the threshold): re-reads txt + gt + tm (77 MB total).
__global__ void __launch_bounds__(256) dice2_kernel(
        const float* __restrict__ outputs,
        const float* __restrict__ labels,
        const float* __restrict__ tmask) {
    const int inst = blockIdx.y;
    const int cls  = inst >> 3, b = inst & 7;
    const int ctxt = cls * NMAPS + (NMAPS - 1);
    const float4* __restrict__ s4 = (const float4*)(outputs + ((size_t)b * NCH + ctxt) * HW);
    const float4* __restrict__ g4 = (const float4*)(labels  + ((size_t)b * NCH + ctxt) * HW);
    const float4* __restrict__ m4 = (const float4*)(tmask   + (size_t)b * HW);

    const float thr = g_thr[inst];
    const int   fb  = g_fallback[inst];

    float a0 = 0.f, a1 = 0.f, a2 = 0.f;
    __shared__ float ssum[3];
    if (threadIdx.x < 3) ssum[threadIdx.x] = 0.0f;
    __syncthreads();

    for (int v = blockIdx.x * blockDim.x + threadIdx.x; v < NVEC;
         v += gridDim.x * blockDim.x) {
        float4 sv4 = s4[v], gv4 = g4[v], mv4 = m4[v];
        const float* sv = &sv4.x; const float* gv = &gv4.x; const float* mv = &mv4.x;
#pragma unroll
        for (int j = 0; j < 4; j++) {
            float s = sv[j], g = gv[j], m = mv[j];
            float sel;
            if (fb) sel = m;
            else    sel = (((s >= thr) || (g > 0.5f)) && (m > 0.5f)) ? 1.0f : 0.0f;
            float sig = sigmoidf_fast(s);
            float pp = sig * sel, tt = g * sel;
            a0 += pp * tt; a1 += pp * pp; a2 += tt * tt;
        }
    }

    const int lane = threadIdx.x & 31;
#pragma unroll
    for (int off = 16; off > 0; off >>= 1) {
        a0 += __shfl_down_sync(0xFFFFFFFFu, a0, off);
        a1 += __shfl_down_sync(0xFFFFFFFFu, a1, off);
        a2 += __shfl_down_sync(0xFFFFFFFFu, a2, off);
    }
    if (lane == 0) {
        atomicAdd(&ssum[0], a0);
        atomicAdd(&ssum[1], a1);
        atomicAdd(&ssum[2], a2);
    }
    __syncthreads();
    if (threadIdx.x < 3)
        atomicAdd(&g_sums[inst][threadIdx.x], ssum[threadIdx.x]);
}

__global__ void finalize_kernel(float* __restrict__ out) {
    if (threadIdx.x != 0 || blockIdx.x != 0) return;
    float lt_sum = 0.f, lk_sum = 0.f, loss_sum = 0.f;
    for (int cls = 0; cls < NCLS; cls++) {
        float lt = 0.f, lk = 0.f;
        for (int b = 0; b < NB; b++) {
            const float* s = g_sums[cls * NB + b];
            float a  = s[0], bb = s[1] + EPSF, cc = s[2] + EPSF;
            lt += 1.f - 2.f * a / (bb + cc);
            float lkb = 0.f;
            for (int c = 0; c < NMAPS - 1; c++) {
                float a2 = s[3 + c * 3], b2 = s[4 + c * 3] + EPSF, c2 = s[5 + c * 3] + EPSF;
                lkb += 1.f - 2.f * a2 / (b2 + c2);
            }
            lk += lkb / (float)(NMAPS - 1);
        }
        lt /= (float)NB; lk /= (float)NB;
        lt_sum += lt; lk_sum += lk;
        loss_sum += LAMBDAF * lt + (1.f - LAMBDAF) * lk;
    }
    out[0] = loss_sum / (float)NCLS;
    out[1] = lt_sum   / (float)NCLS;
    out[2] = lk_sum   / (float)NCLS;
}

// ---------------- launch -----------------------------------------------------
extern "C" void kernel_launch(void* const* d_in, const int* in_sizes, int n_in,
                              void* d_out, int out_size) {
    const float* outputs = (const float*)d_in[0];
    const float* labels  = (const float*)d_in[1];
    const float* tmask   = (const float*)d_in[2];
    float* out = (float*)d_out;

    zero_kernel<<<1024, 256>>>();                       // 4MB hist + state
    pass0_kernel<<<dim3(100, NINST), 256>>>(outputs, labels, tmask);
    select16_kernel<<<NINST, 256>>>(0);
    histB_kernel<<<dim3(148, NINST), 256>>>();
    select16_kernel<<<NINST, 256>>>(1);
    dice2_kernel<<<dim3(100, NINST), 256>>>(outputs, labels, tmask);
    finalize_kernel<<<1, 32>>>(out);
}

// round 6
// speedup vs baseline: 1.3393x; 1.3393x over previous
#include <cuda_runtime.h>
#include <cstdint>

#define HW      409600      // 640*640
#define NVEC    (HW/4)      // 102400
#define NHALF   (NVEC/2)    // 51200
#define NCH     12
#define NB      8
#define NCLS    2
#define NINST   16          // NCLS * NB
#define NMAPS   6
#define NKER    (NMAPS-1)   // 5
#define EPSF    1e-4f
#define LAMBDAF 0.7f

// ---------------- scratch (static device globals; no allocation) ------------
__device__ unsigned int  g_keys[(size_t)NINST * HW];    // ~26 MB
__device__ unsigned char g_selk[(size_t)NINST * HW];    // 6.5 MB
__device__ unsigned int  g_hist[NINST][256];
__device__ unsigned int  g_pos[NINST];
__device__ unsigned int  g_negtot[NINST];
__device__ unsigned int  g_prefix[NINST];
__device__ unsigned int  g_k[NINST];
__device__ float         g_thr[NINST];
__device__ int           g_fallback[NINST];
__device__ float         g_sums[NINST][18];  // [0..2] text ; [3+3c..] kernel c

// ---------------- helpers ---------------------------------------------------
__device__ __forceinline__ unsigned int order_key(float x) {
    unsigned int u = __float_as_uint(x);
    u = (u & 0x80000000u) ? ~u : (u | 0x80000000u);
    if (u == 0u) u = 1u;   // reserve 0 as "positive pixel" sentinel
    return u;
}
__device__ __forceinline__ float key_to_float(unsigned int k) {
    unsigned int bits = (k & 0x80000000u) ? (k ^ 0x80000000u) : ~k;
    return __uint_as_float(bits);
}
__device__ __forceinline__ float sigmoidf_fast(float x) {
    return 1.0f / (1.0f + __expf(-x));
}

// ---------------- kernels ---------------------------------------------------
__global__ void zero_kernel() {
    int inst = blockIdx.x, t = threadIdx.x;
    g_hist[inst][t] = 0u;
    if (t < 18) g_sums[inst][t] = 0.0f;
    if (t == 0) {
        g_pos[inst] = 0u; g_negtot[inst] = 0u;
        g_prefix[inst] = 0u; g_k[inst] = 0u; g_fallback[inst] = 0;
    }
}

// Pass 0: stream texts/gt/tm. Builds keys, selk bytes, top-byte smem hist,
// pos/neg counts. 2x front-batched loads for MLP.
__global__ void __launch_bounds__(256) pass0_kernel(
        const float* __restrict__ outputs,
        const float* __restrict__ labels,
        const float* __restrict__ tmask) {
    const int inst = blockIdx.y;
    const int cls  = inst >> 3, b = inst & 7;
    const int ctxt = cls * NMAPS + (NMAPS - 1);
    const float4* __restrict__ s4 = (const float4*)(outputs + ((size_t)b * NCH + ctxt) * HW);
    const float4* __restrict__ g4 = (const float4*)(labels  + ((size_t)b * NCH + ctxt) * HW);
    const float4* __restrict__ m4 = (const float4*)(tmask   + (size_t)b * HW);
    uint4*        __restrict__ keys4 = (uint4*)(g_keys + (size_t)inst * HW);
    unsigned int* __restrict__ selk4 = (unsigned int*)(g_selk + (size_t)inst * HW);

    __shared__ unsigned int hist[256];
    __shared__ unsigned int spos, sneg;
    for (int i = threadIdx.x; i < 256; i += blockDim.x) hist[i] = 0u;
    if (threadIdx.x == 0) { spos = 0u; sneg = 0u; }
    __syncthreads();

    unsigned int lpos = 0, lneg = 0;
    const int stride = gridDim.x * blockDim.x;
    for (int v = blockIdx.x * blockDim.x + threadIdx.x; v < NHALF; v += stride) {
        // front-batch 6 LDG.128 (two independent vec positions)
        float4 svA = s4[v],         svB = s4[v + NHALF];
        float4 gvA = g4[v],         gvB = g4[v + NHALF];
        float4 mvA = m4[v],         mvB = m4[v + NHALF];

#pragma unroll
        for (int h = 0; h < 2; h++) {
            const float* sv = h ? &svB.x : &svA.x;
            const float* gv = h ? &gvB.x : &gvA.x;
            const float* mv = h ? &mvB.x : &mvA.x;
            const int vv = v + h * NHALF;
            uint4 kout; kout.x = kout.y = kout.z = kout.w = 0u;
            unsigned int* kp = &kout.x;
            unsigned int selkw = 0u;
#pragma unroll
            for (int j = 0; j < 4; j++) {
                float s = sv[j], g = gv[j], m = mv[j];
                if (g <= 0.5f) {
                    unsigned int key = order_key(s);
                    kp[j] = key;
                    atomicAdd(&hist[key >> 24], 1u);
                    lneg++;
                } else if (m > 0.5f) {
                    lpos++;
                }
                // selk = sigmoid(s)>0.5 && m>0.5  ==  s>0 && m>0.5
                if ((s > 0.0f) && (m > 0.5f)) selkw |= (1u << (j * 8));
            }
            keys4[vv] = kout;
            selk4[vv] = selkw;
        }
    }
    atomicAdd(&spos, lpos);
    atomicAdd(&sneg, lneg);
    __syncthreads();
    for (int i = threadIdx.x; i < 256; i += blockDim.x)
        if (hist[i]) atomicAdd(&g_hist[inst][i], hist[i]);
    if (threadIdx.x == 0) {
        if (spos) atomicAdd(&g_pos[inst], spos);
        if (sneg) atomicAdd(&g_negtot[inst], sneg);
    }
}

// Kernel-channel dice: one (inst, channel) per blockIdx.y group.
// Reads 2 float4 streams + selk bytes; only 3 accumulators.
__global__ void __launch_bounds__(256) kdice_kernel(
        const float* __restrict__ outputs,
        const float* __restrict__ labels) {
    const int group = blockIdx.y;
    const int inst = group / NKER, c = group % NKER;
    const int cls  = inst >> 3, b = inst & 7;
    const float4* __restrict__ k4  = (const float4*)(outputs + ((size_t)b * NCH + cls * NMAPS + c) * HW);
    const float4* __restrict__ gk4 = (const float4*)(labels  + ((size_t)b * NCH + cls * NMAPS + c) * HW);
    const unsigned int* __restrict__ selk4 = (const unsigned int*)(g_selk + (size_t)inst * HW);

    float a0 = 0.f, a1 = 0.f, a2 = 0.f;
    __shared__ float ssum[3];
    if (threadIdx.x < 3) ssum[threadIdx.x] = 0.0f;
    __syncthreads();

    const int stride = gridDim.x * blockDim.x;
    for (int v = blockIdx.x * blockDim.x + threadIdx.x; v < NHALF; v += stride) {
        float4 kvA = k4[v],  kvB = k4[v + NHALF];
        float4 gvA = gk4[v], gvB = gk4[v + NHALF];
        unsigned int selA = selk4[v], selB = selk4[v + NHALF];

#pragma unroll
        for (int h = 0; h < 2; h++) {
            const float* kv = h ? &kvB.x : &kvA.x;
            const float* gv = h ? &gvB.x : &gvA.x;
            unsigned int sw = h ? selB : selA;
#pragma unroll
            for (int j = 0; j < 4; j++) {
                float selk = (float)((sw >> (j * 8)) & 1u);
                float sk = sigmoidf_fast(kv[j]);
                float p2 = sk * selk, t2 = gv[j] * selk;
                a0 += p2 * t2; a1 += p2 * p2; a2 += t2 * t2;
            }
        }
    }

    const int lane = threadIdx.x & 31;
#pragma unroll
    for (int off = 16; off > 0; off >>= 1) {
        a0 += __shfl_down_sync(0xFFFFFFFFu, a0, off);
        a1 += __shfl_down_sync(0xFFFFFFFFu, a1, off);
        a2 += __shfl_down_sync(0xFFFFFFFFu, a2, off);
    }
    if (lane == 0) {
        atomicAdd(&ssum[0], a0); atomicAdd(&ssum[1], a1); atomicAdd(&ssum[2], a2);
    }
    __syncthreads();
    if (threadIdx.x < 3)
        atomicAdd(&g_sums[inst][3 + c * 3 + threadIdx.x], ssum[threadIdx.x]);
}

// Consume histogram for this radix pass, pick byte, update prefix & k, zero hist.
__global__ void select_kernel(int pass) {
    const int inst = blockIdx.x;
    __shared__ unsigned int h[256];
    h[threadIdx.x] = g_hist[inst][threadIdx.x];
    __syncthreads();
    g_hist[inst][threadIdx.x] = 0u;   // ready for next pass
    if (threadIdx.x == 0) {
        const int shift = 24 - 8 * pass;
        unsigned int k;
        if (pass == 0) {
            unsigned int pos = g_pos[inst], negt = g_negtot[inst];
            unsigned long long nn = (unsigned long long)pos * 3ull;
            unsigned int neg_num = (unsigned int)(nn < (unsigned long long)negt
                                                      ? nn : (unsigned long long)negt);
            int fb = (pos == 0u) || (neg_num == 0u);
            g_fallback[inst] = fb;
            k = fb ? 1u : neg_num;
        } else {
            k = g_k[inst];
        }
        unsigned int cum = 0; int found = -1;
        for (int bin = 255; bin >= 0; --bin) {
            if (cum + h[bin] >= k) { found = bin; break; }
            cum += h[bin];
        }
        if (found < 0) found = 0;
        g_prefix[inst] |= ((unsigned int)found) << shift;
        g_k[inst] = k - cum;
        if (pass == 3) g_thr[inst] = key_to_float(g_prefix[inst]);
    }
}

// Radix passes 1..3 over the key buffer (2x front-batched uint4 loads).
__global__ void hist_kernel(int shift) {
    const int inst = blockIdx.y;
    const uint4* __restrict__ keys4 = (const uint4*)(g_keys + (size_t)inst * HW);
    const int hishift = shift + 8;
    const unsigned int pfx = g_prefix[inst] >> hishift;

    __shared__ unsigned int hist[256];
    for (int i = threadIdx.x; i < 256; i += blockDim.x) hist[i] = 0u;
    __syncthreads();

    const int stride = gridDim.x * blockDim.x;
    for (int v = blockIdx.x * blockDim.x + threadIdx.x; v < NHALF; v += stride) {
        uint4 kA = keys4[v], kB = keys4[v + NHALF];
#pragma unroll
        for (int h = 0; h < 2; h++) {
            const unsigned int* kp = h ? &kB.x : &kA.x;
#pragma unroll
            for (int j = 0; j < 4; j++) {
                unsigned int key = kp[j];
                if (key != 0u && (key >> hishift) == pfx)
                    atomicAdd(&hist[(key >> shift) & 0xFFu], 1u);
            }
        }
    }
    __syncthreads();
    for (int i = threadIdx.x; i < 256; i += blockDim.x)
        if (hist[i]) atomicAdd(&g_hist[inst][i], hist[i]);
}

// Text dice (needs the threshold): re-reads txt + gt + tm. 2x batched loads.
__global__ void __launch_bounds__(256) dice2_kernel(
        const float* __restrict__ outputs,
        const float* __restrict__ labels,
        const float* __restrict__ tmask) {
    const int inst = blockIdx.y;
    const int cls  = inst >> 3, b = inst & 7;
    const int ctxt = cls * NMAPS + (NMAPS - 1);
    const float4* __restrict__ s4 = (const float4*)(outputs + ((size_t)b * NCH + ctxt) * HW);
    const float4* __restrict__ g4 = (const float4*)(labels  + ((size_t)b * NCH + ctxt) * HW);
    const float4* __restrict__ m4 = (const float4*)(tmask   + (size_t)b * HW);

    const float thr = g_thr[inst];
    const int   fb  = g_fallback[inst];

    float a0 = 0.f, a1 = 0.f, a2 = 0.f;
    __shared__ float ssum[3];
    if (threadIdx.x < 3) ssum[threadIdx.x] = 0.0f;
    __syncthreads();

    const int stride = gridDim.x * blockDim.x;
    for (int v = blockIdx.x * blockDim.x + threadIdx.x; v < NHALF; v += stride) {
        float4 svA = s4[v], svB = s4[v + NHALF];
        float4 gvA = g4[v], gvB = g4[v + NHALF];
        float4 mvA = m4[v], mvB = m4[v + NHALF];
#pragma unroll
        for (int h = 0; h < 2; h++) {
            const float* sv = h ? &svB.x : &svA.x;
            const float* gv = h ? &gvB.x : &gvA.x;
            const float* mv = h ? &mvB.x : &mvA.x;
#pragma unroll
            for (int j = 0; j < 4; j++) {
                float s = sv[j], g = gv[j], m = mv[j];
                float sel;
                if (fb) sel = m;
                else    sel = (((s >= thr) || (g > 0.5f)) && (m > 0.5f)) ? 1.0f : 0.0f;
                float sig = sigmoidf_fast(s);
                float pp = sig * sel, tt = g * sel;
                a0 += pp * tt; a1 += pp * pp; a2 += tt * tt;
            }
        }
    }

    const int lane = threadIdx.x & 31;
#pragma unroll
    for (int off = 16; off > 0; off >>= 1) {
        a0 += __shfl_down_sync(0xFFFFFFFFu, a0, off);
        a1 += __shfl_down_sync(0xFFFFFFFFu, a1, off);
        a2 += __shfl_down_sync(0xFFFFFFFFu, a2, off);
    }
    if (lane == 0) {
        atomicAdd(&ssum[0], a0); atomicAdd(&ssum[1], a1); atomicAdd(&ssum[2], a2);
    }
    __syncthreads();
    if (threadIdx.x < 3)
        atomicAdd(&g_sums[inst][threadIdx.x], ssum[threadIdx.x]);
}

__global__ void finalize_kernel(float* __restrict__ out) {
    if (threadIdx.x != 0 || blockIdx.x != 0) return;
    float lt_sum = 0.f, lk_sum = 0.f, loss_sum = 0.f;
    for (int cls = 0; cls < NCLS; cls++) {
        float lt = 0.f, lk = 0.f;
        for (int b = 0; b < NB; b++) {
            const float* s = g_sums[cls * NB + b];
            float a  = s[0], bb = s[1] + EPSF, cc = s[2] + EPSF;
            lt += 1.f - 2.f * a / (bb + cc);
            float lkb = 0.f;
            for (int c = 0; c < NKER; c++) {
                float a2 = s[3 + c * 3], b2 = s[4 + c * 3] + EPSF, c2 = s[5 + c * 3] + EPSF;
                lkb += 1.f - 2.f * a2 / (b2 + c2);
            }
            lk += lkb / (float)NKER;
        }
        lt /= (float)NB; lk /= (float)NB;
        lt_sum += lt; lk_sum += lk;
        loss_sum += LAMBDAF * lt + (1.f - LAMBDAF) * lk;
    }
    out[0] = loss_sum / (float)NCLS;
    out[1] = lt_sum   / (float)NCLS;
    out[2] = lk_sum   / (float)NCLS;
}

// ---------------- launch -----------------------------------------------------
extern "C" void kernel_launch(void* const* d_in, const int* in_sizes, int n_in,
                              void* d_out, int out_size) {
    const float* outputs = (const float*)d_in[0];
    const float* labels  = (const float*)d_in[1];
    const float* tmask   = (const float*)d_in[2];
    float* out = (float*)d_out;

    zero_kernel<<<NINST, 256>>>();
    pass0_kernel<<<dim3(100, NINST), 256>>>(outputs, labels, tmask);
    kdice_kernel<<<dim3(50, NINST * NKER), 256>>>(outputs, labels);
    select_kernel<<<NINST, 256>>>(0);
    hist_kernel<<<dim3(100, NINST), 256>>>(16);
    select_kernel<<<NINST, 256>>>(1);
    hist_kernel<<<dim3(100, NINST), 256>>>(8);
    select_kernel<<<NINST, 256>>>(2);
    hist_kernel<<<dim3(100, NINST), 256>>>(0);
    select_kernel<<<NINST, 256>>>(3);
    dice2_kernel<<<dim3(100, NINST), 256>>>(outputs, labels, tmask);
    finalize_kernel<<<1, 32>>>(out);
}

// round 9
// speedup vs baseline: 1.5867x; 1.1848x over previous
#include <cuda_runtime.h>
#include <cstdint>

#define HW      409600      // 640*640
#define NVEC    (HW/4)      // 102400
#define NHALF   (NVEC/2)    // 51200
#define NQ      (NVEC/4)    // 25600
#define NCH     12
#define NB      8
#define NCLS    2
#define NINST   16          // NCLS * NB
#define NMAPS   6
#define NKER    (NMAPS-1)   // 5
#define EPSF    1e-4f
#define LAMBDAF 0.7f

// ---------------- scratch (static device globals; no allocation) ------------
__device__ unsigned int  g_keys[(size_t)NINST * HW];    // ~26 MB
__device__ unsigned int  g_buf2[(size_t)NINST * HW];    // ~26 MB (compacted keys)
__device__ unsigned int  g_buf3[(size_t)NINST * HW];    // ~26 MB
__device__ unsigned char g_selk[(size_t)NINST * HW];    // 6.5 MB
__device__ unsigned int  g_histp[4][NINST][256];        // per-radix-pass histograms
__device__ unsigned int  g_cnt2[NINST], g_cnt3[NINST];
__device__ unsigned int  g_pos[NINST];
__device__ unsigned int  g_negtot[NINST];
__device__ float         g_sums[NINST][18];  // [0..2] text ; [3+3c..] kernel c

// ---------------- helpers ---------------------------------------------------
__device__ __forceinline__ unsigned int order_key(float x) {
    unsigned int u = __float_as_uint(x);
    u = (u & 0x80000000u) ? ~u : (u | 0x80000000u);
    if (u == 0u) u = 1u;   // reserve 0 as "positive pixel" sentinel
    return u;
}
__device__ __forceinline__ float key_to_float(unsigned int k) {
    unsigned int bits = (k & 0x80000000u) ? (k ^ 0x80000000u) : ~k;
    return __uint_as_float(bits);
}
__device__ __forceinline__ float sigmoidf_fast(float x) {
    return 1.0f / (1.0f + __expf(-x));
}

// Recompute the radix-selection chain from completed per-pass histograms.
// Block-cooperative (blockDim.x == 256). Returns prefix (top npasses bytes,
// packed little-end at the bottom), residual k, fallback flag.
struct ChainRes { unsigned int prefix; unsigned int k; int fb; };

__device__ ChainRes chain_select(int inst, int npasses) {
    __shared__ unsigned int sfx[256];
    __shared__ unsigned int s_dig, s_k, s_kn;
    __shared__ int s_fb;
    const int t = threadIdx.x;

    if (t == 0) {
        unsigned int pos = g_pos[inst], negt = g_negtot[inst];
        unsigned long long nn = (unsigned long long)pos * 3ull;
        unsigned int neg_num = (unsigned int)(nn < (unsigned long long)negt
                                                  ? nn : (unsigned long long)negt);
        s_fb = (pos == 0u) || (neg_num == 0u);
        s_k  = s_fb ? 1u : neg_num;
    }
    __syncthreads();

    unsigned int prefix = 0u;
    for (int p = 0; p < npasses; p++) {
        sfx[t] = g_histp[p][inst][t];
        if (t == 0) s_dig = 0u;
        __syncthreads();
        // inclusive suffix sum: sfx[t] = sum_{i>=t} hist[i]
#pragma unroll
        for (int off = 1; off < 256; off <<= 1) {
            unsigned int add = (t + off < 256) ? sfx[t + off] : 0u;
            __syncthreads();
            sfx[t] += add;
            __syncthreads();
        }
        unsigned int k = s_k;
        __syncthreads();
        unsigned int nxt = (t < 255) ? sfx[t + 1] : 0u;
        if (sfx[t] >= k && nxt < k) {   // unique winner (sfx non-increasing)
            s_dig = (unsigned int)t;
            s_kn  = k - nxt;
        }
        __syncthreads();
        prefix = (prefix << 8) | s_dig;
        if (t == 0) s_k = s_kn;         // stale-safe: only read next pass
        __syncthreads();
    }
    ChainRes r; r.prefix = prefix; r.k = s_k; r.fb = s_fb;
    return r;
}

// Warp-aggregated compaction append. All 32 lanes must participate.
__device__ __forceinline__ void warp_append(bool match, unsigned int key,
                                            unsigned int* cnt,
                                            unsigned int* __restrict__ dst) {
    unsigned int mask = __ballot_sync(0xFFFFFFFFu, match);
    if (mask) {
        int lane = threadIdx.x & 31;
        int leader = __ffs(mask) - 1;
        unsigned int base = 0;
        if (lane == leader) base = atomicAdd(cnt, (unsigned int)__popc(mask));
        base = __shfl_sync(0xFFFFFFFFu, base, leader);
        if (match) {
            int rank = __popc(mask & ((1u << lane) - 1u));
            dst[base + rank] = key;
        }
    }
}

// ---------------- kernels ---------------------------------------------------
__global__ void zero_kernel() {
    const int inst = blockIdx.x, t = threadIdx.x;
#pragma unroll
    for (int p = 0; p < 4; p++) g_histp[p][inst][t] = 0u;
    if (t < 18) g_sums[inst][t] = 0.0f;
    if (t == 0) {
        g_pos[inst] = 0u; g_negtot[inst] = 0u;
        g_cnt2[inst] = 0u; g_cnt3[inst] = 0u;
    }
}

// Pass 0: stream texts/gt/tm. Builds keys, selk bytes, top-byte hist, counts.
__global__ void __launch_bounds__(256) pass0_kernel(
        const float* __restrict__ outputs,
        const float* __restrict__ labels,
        const float* __restrict__ tmask) {
    const int inst = blockIdx.y;
    const int cls  = inst >> 3, b = inst & 7;
    const int ctxt = cls * NMAPS + (NMAPS - 1);
    const float4* __restrict__ s4 = (const float4*)(outputs + ((size_t)b * NCH + ctxt) * HW);
    const float4* __restrict__ g4 = (const float4*)(labels  + ((size_t)b * NCH + ctxt) * HW);
    const float4* __restrict__ m4 = (const float4*)(tmask   + (size_t)b * HW);
    uint4*        __restrict__ keys4 = (uint4*)(g_keys + (size_t)inst * HW);
    unsigned int* __restrict__ selk4 = (unsigned int*)(g_selk + (size_t)inst * HW);

    __shared__ unsigned int hist[256];
    __shared__ unsigned int spos, sneg;
    for (int i = threadIdx.x; i < 256; i += blockDim.x) hist[i] = 0u;
    if (threadIdx.x == 0) { spos = 0u; sneg = 0u; }
    __syncthreads();

    unsigned int lpos = 0, lneg = 0;
    const int stride = gridDim.x * blockDim.x;
    for (int v = blockIdx.x * blockDim.x + threadIdx.x; v < NHALF; v += stride) {
        float4 svA = s4[v], svB = s4[v + NHALF];
        float4 gvA = g4[v], gvB = g4[v + NHALF];
        float4 mvA = m4[v], mvB = m4[v + NHALF];
#pragma unroll
        for (int h = 0; h < 2; h++) {
            const float* sv = h ? &svB.x : &svA.x;
            const float* gv = h ? &gvB.x : &gvA.x;
            const float* mv = h ? &mvB.x : &mvA.x;
            const int vv = v + h * NHALF;
            uint4 kout; kout.x = kout.y = kout.z = kout.w = 0u;
            unsigned int* kp = &kout.x;
            unsigned int selkw = 0u;
#pragma unroll
            for (int j = 0; j < 4; j++) {
                float s = sv[j], g = gv[j], m = mv[j];
                if (g <= 0.5f) {
                    unsigned int key = order_key(s);
                    kp[j] = key;
                    atomicAdd(&hist[key >> 24], 1u);
                    lneg++;
                } else if (m > 0.5f) {
                    lpos++;
                }
                if ((s > 0.0f) && (m > 0.5f)) selkw |= (1u << (j * 8));
            }
            keys4[vv] = kout;
            selk4[vv] = selkw;
        }
    }
    atomicAdd(&spos, lpos);
    atomicAdd(&sneg, lneg);
    __syncthreads();
    for (int i = threadIdx.x; i < 256; i += blockDim.x)
        if (hist[i]) atomicAdd(&g_histp[0][inst][i], hist[i]);
    if (threadIdx.x == 0) {
        if (spos) atomicAdd(&g_pos[inst], spos);
        if (sneg) atomicAdd(&g_negtot[inst], sneg);
    }
}

// Radix pass 1: stream full key buffer; hist byte2 of prefix-matching keys;
// compact them into g_buf2.
__global__ void __launch_bounds__(256) hist1_kernel() {
    const int inst = blockIdx.y;
    ChainRes cr = chain_select(inst, 1);
    const unsigned int d3 = cr.prefix;       // top byte

    const uint4* __restrict__ keys4 = (const uint4*)(g_keys + (size_t)inst * HW);
    unsigned int* __restrict__ dst = g_buf2 + (size_t)inst * HW;

    __shared__ unsigned int hist[256];
    for (int i = threadIdx.x; i < 256; i += blockDim.x) hist[i] = 0u;
    __syncthreads();

    const int stride = gridDim.x * blockDim.x;
    for (int v = blockIdx.x * blockDim.x + threadIdx.x; v < NHALF; v += stride) {
        uint4 kA = keys4[v], kB = keys4[v + NHALF];
#pragma unroll
        for (int h = 0; h < 2; h++) {
            const unsigned int* kp = h ? &kB.x : &kA.x;
#pragma unroll
            for (int j = 0; j < 4; j++) {
                unsigned int key = kp[j];
                bool match = (key != 0u) && ((key >> 24) == d3);
                if (match) atomicAdd(&hist[(key >> 16) & 0xFFu], 1u);
                warp_append(match, key, &g_cnt2[inst], dst);
            }
        }
    }
    __syncthreads();
    for (int i = threadIdx.x; i < 256; i += blockDim.x)
        if (hist[i]) atomicAdd(&g_histp[1][inst][i], hist[i]);
}

// Radix pass 2: over compacted buf2; hist byte1 of matching; compact to buf3.
__global__ void __launch_bounds__(256) hist2_kernel() {
    const int inst = blockIdx.y;
    ChainRes cr = chain_select(inst, 2);
    const unsigned int d2 = cr.prefix & 0xFFu;

    const unsigned int cnt = g_cnt2[inst];
    const unsigned int cnt_pad = (cnt + 31u) & ~31u;
    const unsigned int* __restrict__ src = g_buf2 + (size_t)inst * HW;
    unsigned int* __restrict__ dst = g_buf3 + (size_t)inst * HW;

    __shared__ unsigned int hist[256];
    for (int i = threadIdx.x; i < 256; i += blockDim.x) hist[i] = 0u;
    __syncthreads();

    const unsigned int stride = gridDim.x * blockDim.x;
    for (unsigned int v = blockIdx.x * blockDim.x + threadIdx.x; v < cnt_pad; v += stride) {
        bool valid = v < cnt;
        unsigned int key = valid ? src[v] : 0u;
        bool match = valid && (((key >> 16) & 0xFFu) == d2);
        if (match) atomicAdd(&hist[(key >> 8) & 0xFFu], 1u);
        warp_append(match, key, &g_cnt3[inst], dst);
    }
    __syncthreads();
    for (int i = threadIdx.x; i < 256; i += blockDim.x)
        if (hist[i]) atomicAdd(&g_histp[2][inst][i], hist[i]);
}

// Radix pass 3: over buf3; hist low byte of matching keys.
__global__ void __launch_bounds__(256) hist3_kernel() {
    const int inst = blockIdx.y;
    ChainRes cr = chain_select(inst, 3);
    const unsigned int d1 = cr.prefix & 0xFFu;

    const unsigned int cnt = g_cnt3[inst];
    const unsigned int* __restrict__ src = g_buf3 + (size_t)inst * HW;

    __shared__ unsigned int hist[256];
    for (int i = threadIdx.x; i < 256; i += blockDim.x) hist[i] = 0u;
    __syncthreads();

    const unsigned int stride = gridDim.x * blockDim.x;
    for (unsigned int v = blockIdx.x * blockDim.x + threadIdx.x; v < cnt; v += stride) {
        unsigned int key = src[v];
        if (((key >> 8) & 0xFFu) == d1)
            atomicAdd(&hist[key & 0xFFu], 1u);
    }
    __syncthreads();
    for (int i = threadIdx.x; i < 256; i += blockDim.x)
        if (hist[i]) atomicAdd(&g_histp[3][inst][i], hist[i]);
}

// Fused dice: y-groups 0..79 = kernel-channel dice; 80..95 = text dice.
__global__ void __launch_bounds__(256) dice_all_kernel(
        const float* __restrict__ outputs,
        const float* __restrict__ labels,
        const float* __restrict__ tmask) {
    const int group = blockIdx.y;
    __shared__ float ssum[3];
    if (threadIdx.x < 3) ssum[threadIdx.x] = 0.0f;

    const int stride = gridDim.x * blockDim.x;
    const int tid0 = blockIdx.x * blockDim.x + threadIdx.x;
    float a0 = 0.f, a1 = 0.f, a2 = 0.f;

    if (group < NINST * NKER) {
        // ---- kernel-channel dice ----
        const int inst = group / NKER, c = group % NKER;
        const int cls  = inst >> 3, b = inst & 7;
        const float4* __restrict__ k4  = (const float4*)(outputs + ((size_t)b * NCH + cls * NMAPS + c) * HW);
        const float4* __restrict__ gk4 = (const float4*)(labels  + ((size_t)b * NCH + cls * NMAPS + c) * HW);
        const unsigned int* __restrict__ selk4 = (const unsigned int*)(g_selk + (size_t)inst * HW);
        __syncthreads();

        for (int v = tid0; v < NQ; v += stride) {
            float4 kv[4], gv[4];
            unsigned int sw[4];
#pragma unroll
            for (int q = 0; q < 4; q++) {
                kv[q] = k4 [v + q * NQ];
                gv[q] = gk4[v + q * NQ];
                sw[q] = selk4[v + q * NQ];
            }
#pragma unroll
            for (int q = 0; q < 4; q++) {
                const float* kp = &kv[q].x;
                const float* gp = &gv[q].x;
#pragma unroll
                for (int j = 0; j < 4; j++) {
                    float selk = (float)((sw[q] >> (j * 8)) & 1u);
                    float sk = sigmoidf_fast(kp[j]);
                    float p2 = sk * selk, t2 = gp[j] * selk;
                    a0 += p2 * t2; a1 += p2 * p2; a2 += t2 * t2;
                }
            }
        }

        const int lane = threadIdx.x & 31;
#pragma unroll
        for (int off = 16; off > 0; off >>= 1) {
            a0 += __shfl_down_sync(0xFFFFFFFFu, a0, off);
            a1 += __shfl_down_sync(0xFFFFFFFFu, a1, off);
            a2 += __shfl_down_sync(0xFFFFFFFFu, a2, off);
        }
        if (lane == 0) {
            atomicAdd(&ssum[0], a0); atomicAdd(&ssum[1], a1); atomicAdd(&ssum[2], a2);
        }
        __syncthreads();
        if (threadIdx.x < 3)
            atomicAdd(&g_sums[inst][3 + c * 3 + threadIdx.x], ssum[threadIdx.x]);
    } else {
        // ---- text dice (needs exact threshold) ----
        const int inst = group - NINST * NKER;
        const int cls  = inst >> 3, b = inst & 7;
        const int ctxt = cls * NMAPS + (NMAPS - 1);
        const float4* __restrict__ s4 = (const float4*)(outputs + ((size_t)b * NCH + ctxt) * HW);
        const float4* __restrict__ g4 = (const float4*)(labels  + ((size_t)b * NCH + ctxt) * HW);
        const float4* __restrict__ m4 = (const float4*)(tmask   + (size_t)b * HW);

        ChainRes cr = chain_select(inst, 4);   // includes __syncthreads
        const float thr = key_to_float(cr.prefix);
        const int   fb  = cr.fb;

        for (int v = tid0; v < NQ; v += stride) {
            float4 sv[4], gv[4], mv[4];
#pragma unroll
            for (int q = 0; q < 4; q++) {
                sv[q] = s4[v + q * NQ];
                gv[q] = g4[v + q * NQ];
                mv[q] = m4[v + q * NQ];
            }
#pragma unroll
            for (int q = 0; q < 4; q++) {
                const float* sp = &sv[q].x;
                const float* gp = &gv[q].x;
                const float* mp = &mv[q].x;
#pragma unroll
                for (int j = 0; j < 4; j++) {
                    float s = sp[j], g = gp[j], m = mp[j];
                    float sel;
                    if (fb) sel = m;
                    else    sel = (((s >= thr) || (g > 0.5f)) && (m > 0.5f)) ? 1.0f : 0.0f;
                    float sig = sigmoidf_fast(s);
                    float pp = sig * sel, tt = g * sel;
                    a0 += pp * tt; a1 += pp * pp; a2 += tt * tt;
                }
            }
        }

        const int lane = threadIdx.x & 31;
#pragma unroll
        for (int off = 16; off > 0; off >>= 1) {
            a0 += __shfl_down_sync(0xFFFFFFFFu, a0, off);
            a1 += __shfl_down_sync(0xFFFFFFFFu, a1, off);
            a2 += __shfl_down_sync(0xFFFFFFFFu, a2, off);
        }
        if (lane == 0) {
            atomicAdd(&ssum[0], a0); atomicAdd(&ssum[1], a1); atomicAdd(&ssum[2], a2);
        }
        __syncthreads();
        if (threadIdx.x < 3)
            atomicAdd(&g_sums[inst][threadIdx.x], ssum[threadIdx.x]);
    }
}

__global__ void finalize_kernel(float* __restrict__ out) {
    if (threadIdx.x != 0 || blockIdx.x != 0) return;
    float lt_sum = 0.f, lk_sum = 0.f, loss_sum = 0.f;
    for (int cls = 0; cls < NCLS; cls++) {
        float lt = 0.f, lk = 0.f;
        for (int b = 0; b < NB; b++) {
            const float* s = g_sums[cls * NB + b];
            float a  = s[0], bb = s[1] + EPSF, cc = s[2] + EPSF;
            lt += 1.f - 2.f * a / (bb + cc);
            float lkb = 0.f;
            for (int c = 0; c < NKER; c++) {
                float a2 = s[3 + c * 3], b2 = s[4 + c * 3] + EPSF, c2 = s[5 + c * 3] + EPSF;
                lkb += 1.f - 2.f * a2 / (b2 + c2);
            }
            lk += lkb / (float)NKER;
        }
        lt /= (float)NB; lk /= (float)NB;
        lt_sum += lt; lk_sum += lk;
        loss_sum += LAMBDAF * lt + (1.f - LAMBDAF) * lk;
    }
    out[0] = loss_sum / (float)NCLS;
    out[1] = lt_sum   / (float)NCLS;
    out[2] = lk_sum   / (float)NCLS;
}

// ---------------- launch -----------------------------------------------------
extern "C" void kernel_launch(void* const* d_in, const int* in_sizes, int n_in,
                              void* d_out, int out_size) {
    const float* outputs = (const float*)d_in[0];
    const float* labels  = (const float*)d_in[1];
    const float* tmask   = (const float*)d_in[2];
    float* out = (float*)d_out;

    zero_kernel<<<NINST, 256>>>();
    pass0_kernel<<<dim3(100, NINST), 256>>>(outputs, labels, tmask);
    hist1_kernel<<<dim3(100, NINST), 256>>>();
    hist2_kernel<<<dim3(50, NINST), 256>>>();
    hist3_kernel<<<dim3(50, NINST), 256>>>();
    dice_all_kernel<<<dim3(50, NINST * NKER + NINST), 256>>>(outputs, labels, tmask);
    finalize_kernel<<<1, 32>>>(out);
}

// round 10
// speedup vs baseline: 1.7271x; 1.0885x over previous
#include <cuda_runtime.h>
#include <cstdint>

#define HW      409600      // 640*640
#define NVEC    (HW/4)      // 102400
#define NHALF   (NVEC/2)    // 51200
#define NQ      (NVEC/4)    // 25600
#define NCH     12
#define NB      8
#define NCLS    2
#define NINST   16          // NCLS * NB
#define NMAPS   6
#define NKER    (NMAPS-1)   // 5
#define EPSF    1e-4f
#define LAMBDAF 0.7f

// ---------------- scratch (static device globals; no allocation) ------------
__device__ unsigned int  g_keys[(size_t)NINST * HW];    // ~26 MB
__device__ unsigned int  g_buf2[(size_t)NINST * HW];    // ~26 MB (compacted keys)
__device__ unsigned char g_selk[(size_t)NINST * HW];    // 6.5 MB
__device__ unsigned int  g_histp[2][NINST][256];        // radix pass 0/1 histograms
__device__ unsigned int  g_cnt2[NINST];
__device__ unsigned int  g_pos[NINST];
__device__ unsigned int  g_negtot[NINST];
__device__ float         g_thr[NINST];
__device__ int           g_fb[NINST];
__device__ float         g_sums[NINST][18];  // [0..2] text ; [3+3c..] kernel c

// ---------------- helpers ---------------------------------------------------
__device__ __forceinline__ unsigned int order_key(float x) {
    unsigned int u = __float_as_uint(x);
    u = (u & 0x80000000u) ? ~u : (u | 0x80000000u);
    if (u == 0u) u = 1u;   // reserve 0 as "positive pixel" sentinel
    return u;
}
__device__ __forceinline__ float key_to_float(unsigned int k) {
    unsigned int bits = (k & 0x80000000u) ? (k ^ 0x80000000u) : ~k;
    return __uint_as_float(bits);
}
__device__ __forceinline__ float sigmoidf_fast(float x) {
    return 1.0f / (1.0f + __expf(-x));
}

// Compute fb + initial k from pos/neg counts (uniform across threads).
__device__ __forceinline__ void ohem_k(int inst, int& fb, unsigned int& k) {
    unsigned int pos = g_pos[inst], negt = g_negtot[inst];
    unsigned long long nn = (unsigned long long)pos * 3ull;
    unsigned int neg_num = (unsigned int)(nn < (unsigned long long)negt
                                              ? nn : (unsigned long long)negt);
    fb = (pos == 0u) || (neg_num == 0u);
    k  = fb ? 1u : neg_num;
}

// Fast order-statistic digit select over a 256-bin histogram.
// Block-cooperative; threads 0..255 participate in work, ALL threads hit bars.
// Finds digit d with suffix(d) >= k > suffix(d+1); returns d and residual k.
// If histogram can't cover k (fallback), digit=0 and k unchanged.
__device__ void fast_chain(const unsigned int* __restrict__ hist,
                           unsigned int& k, unsigned int& digit) {
    __shared__ unsigned int wtot[8];
    __shared__ unsigned int s_dig, s_kn;
    const int t = threadIdx.x;
    const int lane = t & 31, warp = t >> 5;

    if (t == 0) { s_dig = 0u; s_kn = k; }
    unsigned int sfx = 0u;
    if (t < 256) {
        sfx = hist[t];
#pragma unroll
        for (int off = 1; off < 32; off <<= 1) {
            unsigned int u = __shfl_down_sync(0xFFFFFFFFu, sfx, off);
            if (lane + off < 32) sfx += u;
        }
        if (lane == 0) wtot[warp] = sfx;
    }
    __syncthreads();
    if (t < 256) {
        unsigned int tail = 0u;
#pragma unroll
        for (int w = 0; w < 8; w++) if (w > warp) tail += wtot[w];
        sfx += tail;
        unsigned int nxt = __shfl_down_sync(0xFFFFFFFFu, sfx, 1);
        if (lane == 31) nxt = tail;
        if (sfx >= k && nxt < k) { s_dig = (unsigned int)t; s_kn = k - nxt; }
    }
    __syncthreads();
    digit = s_dig; k = s_kn;
    __syncthreads();
}

// Warp-aggregated compaction append. All 32 lanes must participate.
__device__ __forceinline__ void warp_append(bool match, unsigned int key,
                                            unsigned int* cnt,
                                            unsigned int* __restrict__ dst) {
    unsigned int mask = __ballot_sync(0xFFFFFFFFu, match);
    if (mask) {
        int lane = threadIdx.x & 31;
        int leader = __ffs(mask) - 1;
        unsigned int base = 0;
        if (lane == leader) base = atomicAdd(cnt, (unsigned int)__popc(mask));
        base = __shfl_sync(0xFFFFFFFFu, base, leader);
        if (match) {
            int rank = __popc(mask & ((1u << lane) - 1u));
            dst[base + rank] = key;
        }
    }
}

// ---------------- kernels ---------------------------------------------------
__global__ void zero_kernel() {
    const int inst = blockIdx.x, t = threadIdx.x;
    g_histp[0][inst][t] = 0u;
    g_histp[1][inst][t] = 0u;
    if (t < 18) g_sums[inst][t] = 0.0f;
    if (t == 0) {
        g_pos[inst] = 0u; g_negtot[inst] = 0u; g_cnt2[inst] = 0u;
    }
}

// Pass 0: stream texts/gt/tm. Builds keys, selk bytes, top-byte hist, counts.
__global__ void __launch_bounds__(256) pass0_kernel(
        const float* __restrict__ outputs,
        const float* __restrict__ labels,
        const float* __restrict__ tmask) {
    const int inst = blockIdx.y;
    const int cls  = inst >> 3, b = inst & 7;
    const int ctxt = cls * NMAPS + (NMAPS - 1);
    const float4* __restrict__ s4 = (const float4*)(outputs + ((size_t)b * NCH + ctxt) * HW);
    const float4* __restrict__ g4 = (const float4*)(labels  + ((size_t)b * NCH + ctxt) * HW);
    const float4* __restrict__ m4 = (const float4*)(tmask   + (size_t)b * HW);
    uint4*        __restrict__ keys4 = (uint4*)(g_keys + (size_t)inst * HW);
    unsigned int* __restrict__ selk4 = (unsigned int*)(g_selk + (size_t)inst * HW);

    __shared__ unsigned int hist[256];
    __shared__ unsigned int spos, sneg;
    for (int i = threadIdx.x; i < 256; i += blockDim.x) hist[i] = 0u;
    if (threadIdx.x == 0) { spos = 0u; sneg = 0u; }
    __syncthreads();

    unsigned int lpos = 0, lneg = 0;
    const int stride = gridDim.x * blockDim.x;
    for (int v = blockIdx.x * blockDim.x + threadIdx.x; v < NHALF; v += stride) {
        float4 svA = s4[v], svB = s4[v + NHALF];
        float4 gvA = g4[v], gvB = g4[v + NHALF];
        float4 mvA = m4[v], mvB = m4[v + NHALF];
#pragma unroll
        for (int h = 0; h < 2; h++) {
            const float* sv = h ? &svB.x : &svA.x;
            const float* gv = h ? &gvB.x : &gvA.x;
            const float* mv = h ? &mvB.x : &mvA.x;
            const int vv = v + h * NHALF;
            uint4 kout; kout.x = kout.y = kout.z = kout.w = 0u;
            unsigned int* kp = &kout.x;
            unsigned int selkw = 0u;
#pragma unroll
            for (int j = 0; j < 4; j++) {
                float s = sv[j], g = gv[j], m = mv[j];
                if (g <= 0.5f) {
                    unsigned int key = order_key(s);
                    kp[j] = key;
                    atomicAdd(&hist[key >> 24], 1u);
                    lneg++;
                } else if (m > 0.5f) {
                    lpos++;
                }
                if ((s > 0.0f) && (m > 0.5f)) selkw |= (1u << (j * 8));
            }
            keys4[vv] = kout;
            selk4[vv] = selkw;
        }
    }
    atomicAdd(&spos, lpos);
    atomicAdd(&sneg, lneg);
    __syncthreads();
    for (int i = threadIdx.x; i < 256; i += blockDim.x)
        if (hist[i]) atomicAdd(&g_histp[0][inst][i], hist[i]);
    if (threadIdx.x == 0) {
        if (spos) atomicAdd(&g_pos[inst], spos);
        if (sneg) atomicAdd(&g_negtot[inst], sneg);
    }
}

// Radix pass 1: stream full key buffer; hist byte2 of prefix-matching keys;
// compact them into g_buf2.
__global__ void __launch_bounds__(256) hist1_kernel() {
    const int inst = blockIdx.y;
    int fb; unsigned int k;
    ohem_k(inst, fb, k);
    unsigned int d3;
    fast_chain(g_histp[0][inst], k, d3);

    const uint4* __restrict__ keys4 = (const uint4*)(g_keys + (size_t)inst * HW);
    unsigned int* __restrict__ dst = g_buf2 + (size_t)inst * HW;

    __shared__ unsigned int hist[256];
    for (int i = threadIdx.x; i < 256; i += blockDim.x) hist[i] = 0u;
    __syncthreads();

    const int stride = gridDim.x * blockDim.x;
    for (int v = blockIdx.x * blockDim.x + threadIdx.x; v < NHALF; v += stride) {
        uint4 kA = keys4[v], kB = keys4[v + NHALF];
#pragma unroll
        for (int h = 0; h < 2; h++) {
            const unsigned int* kp = h ? &kB.x : &kA.x;
#pragma unroll
            for (int j = 0; j < 4; j++) {
                unsigned int key = kp[j];
                bool match = (key != 0u) && ((key >> 24) == d3);
                if (match) atomicAdd(&hist[(key >> 16) & 0xFFu], 1u);
                warp_append(match, key, &g_cnt2[inst], dst);
            }
        }
    }
    __syncthreads();
    for (int i = threadIdx.x; i < 256; i += blockDim.x)
        if (hist[i]) atomicAdd(&g_histp[1][inst][i], hist[i]);
}

// Tail: one block per instance. Finishes radix passes 2 and 3 over the
// compacted buf2 (local smem hists) and writes the final threshold.
__global__ void __launch_bounds__(256) tail_kernel() {
    const int inst = blockIdx.x;
    int fb; unsigned int k;
    ohem_k(inst, fb, k);

    unsigned int d3, d2, d1, d0;
    fast_chain(g_histp[0][inst], k, d3);    // re-derive d3 + residual k
    fast_chain(g_histp[1][inst], k, d2);    // d2 + residual k

    const unsigned int cnt = g_cnt2[inst];
    const unsigned int* __restrict__ src = g_buf2 + (size_t)inst * HW;

    __shared__ unsigned int sh[256];
    sh[threadIdx.x] = 0u;
    __syncthreads();
    for (unsigned int v = threadIdx.x; v < cnt; v += blockDim.x) {
        unsigned int key = src[v];
        if (((key >> 16) & 0xFFu) == d2)
            atomicAdd(&sh[(key >> 8) & 0xFFu], 1u);
    }
    __syncthreads();
    fast_chain(sh, k, d1);

    sh[threadIdx.x] = 0u;
    __syncthreads();
    for (unsigned int v = threadIdx.x; v < cnt; v += blockDim.x) {
        unsigned int key = src[v];
        if ((((key >> 16) & 0xFFu) == d2) && (((key >> 8) & 0xFFu) == d1))
            atomicAdd(&sh[key & 0xFFu], 1u);
    }
    __syncthreads();
    fast_chain(sh, k, d0);

    if (threadIdx.x == 0) {
        unsigned int prefix = (d3 << 24) | (d2 << 16) | (d1 << 8) | d0;
        g_thr[inst] = key_to_float(prefix);
        g_fb[inst]  = fb;
    }
}

// Fused dice: y-groups 0..79 = kernel-channel dice; 80..95 = text dice.
__global__ void __launch_bounds__(256) dice_all_kernel(
        const float* __restrict__ outputs,
        const float* __restrict__ labels,
        const float* __restrict__ tmask) {
    const int group = blockIdx.y;
    __shared__ float ssum[3];
    if (threadIdx.x < 3) ssum[threadIdx.x] = 0.0f;
    __syncthreads();

    const int stride = gridDim.x * blockDim.x;
    const int tid0 = blockIdx.x * blockDim.x + threadIdx.x;
    float a0 = 0.f, a1 = 0.f, a2 = 0.f;

    if (group < NINST * NKER) {
        // ---- kernel-channel dice ----
        const int inst = group / NKER, c = group % NKER;
        const int cls  = inst >> 3, b = inst & 7;
        const float4* __restrict__ k4  = (const float4*)(outputs + ((size_t)b * NCH + cls * NMAPS + c) * HW);
        const float4* __restrict__ gk4 = (const float4*)(labels  + ((size_t)b * NCH + cls * NMAPS + c) * HW);
        const unsigned int* __restrict__ selk4 = (const unsigned int*)(g_selk + (size_t)inst * HW);

        for (int v = tid0; v < NQ; v += stride) {
            float4 kv[4], gv[4];
            unsigned int sw[4];
#pragma unroll
            for (int q = 0; q < 4; q++) {
                kv[q] = k4 [v + q * NQ];
                gv[q] = gk4[v + q * NQ];
                sw[q] = selk4[v + q * NQ];
            }
#pragma unroll
            for (int q = 0; q < 4; q++) {
                const float* kp = &kv[q].x;
                const float* gp = &gv[q].x;
#pragma unroll
                for (int j = 0; j < 4; j++) {
                    float selk = (float)((sw[q] >> (j * 8)) & 1u);
                    float sk = sigmoidf_fast(kp[j]);
                    float p2 = sk * selk, t2 = gp[j] * selk;
                    a0 += p2 * t2; a1 += p2 * p2; a2 += t2 * t2;
                }
            }
        }

        const int lane = threadIdx.x & 31;
#pragma unroll
        for (int off = 16; off > 0; off >>= 1) {
            a0 += __shfl_down_sync(0xFFFFFFFFu, a0, off);
            a1 += __shfl_down_sync(0xFFFFFFFFu, a1, off);
            a2 += __shfl_down_sync(0xFFFFFFFFu, a2, off);
        }
        if (lane == 0) {
            atomicAdd(&ssum[0], a0); atomicAdd(&ssum[1], a1); atomicAdd(&ssum[2], a2);
        }
        __syncthreads();
        if (threadIdx.x < 3)
            atomicAdd(&g_sums[inst][3 + c * 3 + threadIdx.x], ssum[threadIdx.x]);
    } else {
        // ---- text dice (threshold precomputed by tail_kernel) ----
        const int inst = group - NINST * NKER;
        const int cls  = inst >> 3, b = inst & 7;
        const int ctxt = cls * NMAPS + (NMAPS - 1);
        const float4* __restrict__ s4 = (const float4*)(outputs + ((size_t)b * NCH + ctxt) * HW);
        const float4* __restrict__ g4 = (const float4*)(labels  + ((size_t)b * NCH + ctxt) * HW);
        const float4* __restrict__ m4 = (const float4*)(tmask   + (size_t)b * HW);

        const float thr = g_thr[inst];
        const int   fb  = g_fb[inst];

        for (int v = tid0; v < NQ; v += stride) {
            float4 sv[4], gv[4], mv[4];
#pragma unroll
            for (int q = 0; q < 4; q++) {
                sv[q] = s4[v + q * NQ];
                gv[q] = g4[v + q * NQ];
                mv[q] = m4[v + q * NQ];
            }
#pragma unroll
            for (int q = 0; q < 4; q++) {
                const float* sp = &sv[q].x;
                const float* gp = &gv[q].x;
                const float* mp = &mv[q].x;
#pragma unroll
                for (int j = 0; j < 4; j++) {
                    float s = sp[j], g = gp[j], m = mp[j];
                    float sel;
                    if (fb) sel = m;
                    else    sel = (((s >= thr) || (g > 0.5f)) && (m > 0.5f)) ? 1.0f : 0.0f;
                    float sig = sigmoidf_fast(s);
                    float pp = sig * sel, tt = g * sel;
                    a0 += pp * tt; a1 += pp * pp; a2 += tt * tt;
                }
            }
        }

        const int lane = threadIdx.x & 31;
#pragma unroll
        for (int off = 16; off > 0; off >>= 1) {
            a0 += __shfl_down_sync(0xFFFFFFFFu, a0, off);
            a1 += __shfl_down_sync(0xFFFFFFFFu, a1, off);
            a2 += __shfl_down_sync(0xFFFFFFFFu, a2, off);
        }
        if (lane == 0) {
            atomicAdd(&ssum[0], a0); atomicAdd(&ssum[1], a1); atomicAdd(&ssum[2], a2);
        }
        __syncthreads();
        if (threadIdx.x < 3)
            atomicAdd(&g_sums[inst][threadIdx.x], ssum[threadIdx.x]);
    }
}

__global__ void finalize_kernel(float* __restrict__ out) {
    if (threadIdx.x != 0 || blockIdx.x != 0) return;
    float lt_sum = 0.f, lk_sum = 0.f, loss_sum = 0.f;
    for (int cls = 0; cls < NCLS; cls++) {
        float lt = 0.f, lk = 0.f;
        for (int b = 0; b < NB; b++) {
            const float* s = g_sums[cls * NB + b];
            float a  = s[0], bb = s[1] + EPSF, cc = s[2] + EPSF;
            lt += 1.f - 2.f * a / (bb + cc);
            float lkb = 0.f;
            for (int c = 0; c < NKER; c++) {
                float a2 = s[3 + c * 3], b2 = s[4 + c * 3] + EPSF, c2 = s[5 + c * 3] + EPSF;
                lkb += 1.f - 2.f * a2 / (b2 + c2);
            }
            lk += lkb / (float)NKER;
        }
        lt /= (float)NB; lk /= (float)NB;
        lt_sum += lt; lk_sum += lk;
        loss_sum += LAMBDAF * lt + (1.f - LAMBDAF) * lk;
    }
    out[0] = loss_sum / (float)NCLS;
    out[1] = lt_sum   / (float)NCLS;
    out[2] = lk_sum   / (float)NCLS;
}

// ---------------- launch -----------------------------------------------------
extern "C" void kernel_launch(void* const* d_in, const int* in_sizes, int n_in,
                              void* d_out, int out_size) {
    const float* outputs = (const float*)d_in[0];
    const float* labels  = (const float*)d_in[1];
    const float* tmask   = (const float*)d_in[2];
    float* out = (float*)d_out;

    zero_kernel<<<NINST, 256>>>();
    pass0_kernel<<<dim3(100, NINST), 256>>>(outputs, labels, tmask);
    hist1_kernel<<<dim3(100, NINST), 256>>>();
    tail_kernel<<<NINST, 256>>>();
    dice_all_kernel<<<dim3(50, NINST * NKER + NINST), 256>>>(outputs, labels, tmask);
    finalize_kernel<<<1, 32>>>(out);
}